// round 3
// baseline (speedup 1.0000x reference)
#include <cuda_runtime.h>
#include <cuda_bf16.h>

#define LT_W 0.5f
#define LIN_W 0.1f
#define UNROLL 4

__device__ __forceinline__ float4 sel4(float4 v) {
    v.x = (v.x < LT_W) ? v.x * LIN_W : v.x;
    v.y = (v.y < LT_W) ? v.y * LIN_W : v.y;
    v.z = (v.z < LT_W) ? v.z * LIN_W : v.z;
    v.w = (v.w < LT_W) ? v.w * LIN_W : v.w;
    return v;
}

__global__ void __launch_bounds__(256) apply_lt_lin_v4x4(
    const float4* __restrict__ x, float4* __restrict__ out, int n4)
{
    // Each CTA handles a contiguous chunk of 256*UNROLL float4's.
    int base = blockIdx.x * (256 * UNROLL) + threadIdx.x;

    float4 v[UNROLL];
    // Issue all loads first -> MLP = 4 per thread (streaming, evict-first)
    #pragma unroll
    for (int k = 0; k < UNROLL; k++) {
        int i = base + k * 256;
        if (i < n4) v[k] = __ldcs(&x[i]);
    }
    #pragma unroll
    for (int k = 0; k < UNROLL; k++) {
        int i = base + k * 256;
        if (i < n4) __stcs(&out[i], sel4(v[k]));
    }
}

// Scalar tail for n % 4 != 0 (not hit for this shape, kept for generality)
__global__ void apply_lt_lin_tail(
    const float* __restrict__ x, float* __restrict__ out, int start, int n)
{
    int i = start + blockIdx.x * blockDim.x + threadIdx.x;
    if (i < n) {
        float v = x[i];
        out[i] = (v < LT_W) ? v * LIN_W : v;
    }
}

extern "C" void kernel_launch(void* const* d_in, const int* in_sizes, int n_in,
                              void* d_out, int out_size)
{
    const float* x = (const float*)d_in[0];
    float* out = (float*)d_out;
    int n = in_sizes[0];

    int n4 = n / 4;
    if (n4 > 0) {
        const int per_cta = 256 * UNROLL;
        int blocks = (n4 + per_cta - 1) / per_cta;
        apply_lt_lin_v4x4<<<blocks, 256>>>(
            (const float4*)x, (float4*)out, n4);
    }
    int rem = n - n4 * 4;
    if (rem > 0) {
        apply_lt_lin_tail<<<1, 128>>>(x, out, n4 * 4, n);
    }
}